// round 4
// baseline (speedup 1.0000x reference)
#include <cuda_runtime.h>
#include <cuda_bf16.h>
#include <math.h>

// R2: identical to R1 submission — R1 failed with a broker-level
// "GB300 container failed twice" (no compile/runtime error surfaced).
// Retrying to obtain a baseline measurement.

// ---------------- problem constants ----------------
#define NPOST 100000
#define NUSER 50000
#define NENT  20000
#define HID   64

// relations: 0 publish(u->p), 1 repost(u->p), 2 contain(p->e),
//            3 interact(u->u), 4 follow(u->u), 5 similar(p->p)
static const int REL_E[6]    = {100000, 200000, 200000, 400000, 400000, 250000};
static const int REL_NSRC[6] = {NUSER,  NUSER,  NPOST,  NUSER,  NUSER,  NPOST};
static const int REL_NDST[6] = {NPOST,  NPOST,  NENT,   NUSER,  NUSER,  NPOST};
static const int REL_SRCT[6] = {1,1,0,1,1,0};   // 0=post,1=user,2=ent
static const int REL_DSTT[6] = {0,0,2,1,1,0};
static const int REL_SRCIN[6] = {3,5,7,9,11,13};
static const int REL_DSTIN[6] = {4,6,8,10,12,14};
static const int REL_RPOFF[6] = {0, 100001, 200002, 220003, 270004, 320005}; // rowptr offsets
static const int REL_COLOFF[6]= {0, 100000, 300000, 500000, 900000, 1300000};
#define RP_TOTAL  420006
#define COL_TOTAL 1550000

// ---------------- device scratch (static, no allocation) ----------------
__device__ float g_hA_post[NPOST*64];
__device__ float g_hB_post[NPOST*64];
__device__ float g_hA_user[NUSER*64];
__device__ float g_hB_user[NUSER*64];
__device__ float g_hA_ent [NENT*64];
__device__ float g_hB_ent [NENT*64];
__device__ float g_hs [NPOST*128];
__device__ float g_als[NPOST*2];
__device__ float g_ald[NPOST*2];
__device__ float g_v  [256];          // [0:128) vs, [128:256) vd
__device__ float g_h1 [NPOST*32];
__device__ int   g_rowptr[RP_TOTAL];
__device__ int   g_col   [COL_TOTAL];
__device__ int   g_deg   [NPOST];
__device__ int   g_cursor[NPOST];

// ---------------- kernels ----------------

// C[m][n] = sum_k A[m][k]*W[n][k] (+bias[n]) (optional relu). 64x64 tiles, 256 thr.
__global__ void gemm_nt(const float* __restrict__ A, const float* __restrict__ W,
                        const float* __restrict__ bias, float* __restrict__ C,
                        int M, int N, int K, int do_relu)
{
    __shared__ float As[64][65];
    __shared__ float Wk[64][68];   // [k][n], row stride 272B (16B aligned)
    int m0 = blockIdx.x * 64, n0 = blockIdx.y * 64;
    int tid = threadIdx.x;
    int ty = tid >> 4, tx = tid & 15;
    float acc[4][4] = {{0,0,0,0},{0,0,0,0},{0,0,0,0},{0,0,0,0}};

    for (int k0 = 0; k0 < K; k0 += 64) {
        int kc = K - k0; if (kc > 64) kc = 64;
        #pragma unroll
        for (int i = tid; i < 4096; i += 256) {
            int r = i >> 6, c = i & 63;
            As[r][c] = (m0 + r < M && c < kc) ? A[(size_t)(m0 + r) * K + k0 + c] : 0.f;
            Wk[c][r] = (n0 + r < N && c < kc) ? W[(size_t)(n0 + r) * K + k0 + c] : 0.f;
        }
        __syncthreads();
        #pragma unroll 8
        for (int k = 0; k < 64; k++) {
            float a0 = As[ty*4+0][k], a1 = As[ty*4+1][k];
            float a2 = As[ty*4+2][k], a3 = As[ty*4+3][k];
            float4 b = *(const float4*)&Wk[k][tx*4];
            acc[0][0] = fmaf(a0,b.x,acc[0][0]); acc[0][1] = fmaf(a0,b.y,acc[0][1]);
            acc[0][2] = fmaf(a0,b.z,acc[0][2]); acc[0][3] = fmaf(a0,b.w,acc[0][3]);
            acc[1][0] = fmaf(a1,b.x,acc[1][0]); acc[1][1] = fmaf(a1,b.y,acc[1][1]);
            acc[1][2] = fmaf(a1,b.z,acc[1][2]); acc[1][3] = fmaf(a1,b.w,acc[1][3]);
            acc[2][0] = fmaf(a2,b.x,acc[2][0]); acc[2][1] = fmaf(a2,b.y,acc[2][1]);
            acc[2][2] = fmaf(a2,b.z,acc[2][2]); acc[2][3] = fmaf(a2,b.w,acc[2][3]);
            acc[3][0] = fmaf(a3,b.x,acc[3][0]); acc[3][1] = fmaf(a3,b.y,acc[3][1]);
            acc[3][2] = fmaf(a3,b.z,acc[3][2]); acc[3][3] = fmaf(a3,b.w,acc[3][3]);
        }
        __syncthreads();
    }
    #pragma unroll
    for (int i = 0; i < 4; i++) {
        int row = m0 + ty*4 + i;
        if (row >= M) continue;
        #pragma unroll
        for (int j = 0; j < 4; j++) {
            int cn = n0 + tx*4 + j;
            if (cn >= N) continue;
            float val = acc[i][j] + (bias ? bias[cn] : 0.f);
            if (do_relu) val = fmaxf(val, 0.f);
            C[(size_t)row * N + cn] = val;
        }
    }
}

// vs[h*64+k] = sum_c a_s[h][c]*Wsrc[(h*64+c)][k]; vd likewise. 256 threads.
__global__ void compute_v(const float* __restrict__ Wsrc, const float* __restrict__ Wdst,
                          const float* __restrict__ as_, const float* __restrict__ ad_,
                          float* __restrict__ v)
{
    int t = threadIdx.x;
    const float* W = (t < 128) ? Wsrc : Wdst;
    const float* a = (t < 128) ? as_  : ad_;
    int idx = t & 127, h = idx >> 6, k = idx & 63;
    float s = 0.f;
    #pragma unroll 8
    for (int c = 0; c < 64; c++)
        s = fmaf(a[h*64 + c], W[(h*64 + c)*64 + k], s);
    v[t] = s;
}

// al[n][h] = dot(h[n][0:64], v[h][0:64]); warp per node.
__global__ void aldot(const float* __restrict__ h, const float* __restrict__ v,
                      float* __restrict__ al, int n)
{
    int w = (blockIdx.x * blockDim.x + threadIdx.x) >> 5;
    int lane = threadIdx.x & 31;
    if (w >= n) return;
    float2 x = ((const float2*)(h + (size_t)w * 64))[lane];
    float p0 = x.x * v[lane*2]      + x.y * v[lane*2+1];
    float p1 = x.x * v[64+lane*2]   + x.y * v[64+lane*2+1];
    #pragma unroll
    for (int o = 16; o; o >>= 1) {
        p0 += __shfl_xor_sync(0xffffffffu, p0, o);
        p1 += __shfl_xor_sync(0xffffffffu, p1, o);
    }
    if (lane == 0) ((float2*)al)[w] = make_float2(p0, p1);
}

__device__ __forceinline__ float lrelu(float x) { return x > 0.f ? x : 0.2f * x; }

// warp per dst node: softmax over in-edges (per head) + weighted aggregation.
// out[dst][0:64] += mean_heads(sum_e alpha*hs[src]) + bias
__global__ void gat_aggregate(const int* __restrict__ rowptr, const int* __restrict__ col,
                              const float* __restrict__ hs, const float* __restrict__ als,
                              const float* __restrict__ ald, const float* __restrict__ bias,
                              float* __restrict__ out, int n_dst)
{
    int w = (blockIdx.x * blockDim.x + threadIdx.x) >> 5;
    int lane = threadIdx.x & 31;
    if (w >= n_dst) return;
    int beg = rowptr[w], end = rowptr[w + 1];
    float2 ad = ((const float2*)ald)[w];

    // pass 1: per-head max
    float m0 = -1e30f, m1 = -1e30f;
    for (int e = beg + lane; e < end; e += 32) {
        int s = col[e];
        float2 as2 = ((const float2*)als)[s];
        m0 = fmaxf(m0, lrelu(as2.x + ad.x));
        m1 = fmaxf(m1, lrelu(as2.y + ad.y));
    }
    #pragma unroll
    for (int o = 16; o; o >>= 1) {
        m0 = fmaxf(m0, __shfl_xor_sync(0xffffffffu, m0, o));
        m1 = fmaxf(m1, __shfl_xor_sync(0xffffffffu, m1, o));
    }
    // pass 2: per-head sum
    float s0 = 0.f, s1 = 0.f;
    for (int e = beg + lane; e < end; e += 32) {
        int s = col[e];
        float2 as2 = ((const float2*)als)[s];
        s0 += __expf(lrelu(as2.x + ad.x) - m0);
        s1 += __expf(lrelu(as2.y + ad.y) - m1);
    }
    #pragma unroll
    for (int o = 16; o; o >>= 1) {
        s0 += __shfl_xor_sync(0xffffffffu, s0, o);
        s1 += __shfl_xor_sync(0xffffffffu, s1, o);
    }
    float inv0 = 1.f / (s0 + 1e-16f), inv1 = 1.f / (s1 + 1e-16f);

    // pass 3: accumulate. lane i owns hs components [4i,4i+4): lanes 0-15 head0, 16-31 head1.
    int head = lane >> 4;
    float mh   = head ? m1   : m0;
    float invh = head ? inv1 : inv0;
    float adh  = head ? ad.y : ad.x;
    float a0 = 0.f, a1 = 0.f, a2 = 0.f, a3 = 0.f;
    for (int e = beg; e < end; e++) {
        int s = col[e];                               // broadcast
        float2 as2 = ((const float2*)als)[s];          // broadcast
        float eh = lrelu((head ? as2.y : as2.x) + adh);
        float alpha = __expf(eh - mh) * invh;
        float4 v = ((const float4*)(hs + (size_t)s * 128))[lane];
        a0 = fmaf(alpha, v.x, a0);
        a1 = fmaf(alpha, v.y, a1);
        a2 = fmaf(alpha, v.z, a2);
        a3 = fmaf(alpha, v.w, a3);
    }
    // mean over heads: lane i pairs with lane i+16 (same channel, other head)
    a0 += __shfl_xor_sync(0xffffffffu, a0, 16);
    a1 += __shfl_xor_sync(0xffffffffu, a1, 16);
    a2 += __shfl_xor_sync(0xffffffffu, a2, 16);
    a3 += __shfl_xor_sync(0xffffffffu, a3, 16);
    if (lane < 16) {
        float4 bb = ((const float4*)bias)[lane];
        float* op = out + (size_t)w * 64 + lane * 4;
        op[0] += 0.5f * a0 + bb.x;
        op[1] += 0.5f * a1 + bb.y;
        op[2] += 0.5f * a2 + bb.z;
        op[3] += 0.5f * a3 + bb.w;
    }
}

__global__ void relu_k(float* __restrict__ x, int n)
{
    int i = blockIdx.x * blockDim.x + threadIdx.x;
    if (i < n) x[i] = fmaxf(x[i], 0.f);
}

// out[n] = b2 + dot(h1[n][0:32], w2); warp per row
__global__ void cls2_k(const float* __restrict__ h1, const float* __restrict__ w2,
                       const float* __restrict__ b2, float* __restrict__ out, int n)
{
    int w = (blockIdx.x * blockDim.x + threadIdx.x) >> 5;
    int lane = threadIdx.x & 31;
    if (w >= n) return;
    float p = h1[(size_t)w * 32 + lane] * w2[lane];
    #pragma unroll
    for (int o = 16; o; o >>= 1) p += __shfl_xor_sync(0xffffffffu, p, o);
    if (lane == 0) out[w] = p + b2[0];
}

// ---- CSR build ----
__global__ void hist_k(const int* __restrict__ dst, int* __restrict__ deg, int E)
{
    int i = blockIdx.x * blockDim.x + threadIdx.x;
    if (i < E) atomicAdd(&deg[dst[i]], 1);
}

__global__ void scatter_k(const int* __restrict__ src, const int* __restrict__ dst,
                          int* __restrict__ cursor, int* __restrict__ col, int E)
{
    int i = blockIdx.x * blockDim.x + threadIdx.x;
    if (i < E) {
        int p = atomicAdd(&cursor[dst[i]], 1);
        col[p] = src[i];
    }
}

// single-block exclusive scan, 1024 threads, 8 items/thread per chunk
__global__ void ex_scan(const int* __restrict__ in, int* __restrict__ out, int n)
{
    __shared__ int wsum[32];
    __shared__ int carry_sh;
    int tid = threadIdx.x, lane = tid & 31, wid = tid >> 5;
    if (tid == 0) carry_sh = 0;
    __syncthreads();
    const int CH = 1024 * 8;
    for (int base = 0; base < n; base += CH) {
        int vals[8]; int s = 0;
        int i0 = base + tid * 8;
        #pragma unroll
        for (int j = 0; j < 8; j++) { int i = i0 + j; int v = (i < n) ? in[i] : 0; vals[j] = v; s += v; }
        int ws = s;
        #pragma unroll
        for (int o = 1; o < 32; o <<= 1) { int t = __shfl_up_sync(0xffffffffu, ws, o); if (lane >= o) ws += t; }
        if (lane == 31) wsum[wid] = ws;
        __syncthreads();
        if (wid == 0) {
            int v = wsum[lane], p = v;
            #pragma unroll
            for (int o = 1; o < 32; o <<= 1) { int t = __shfl_up_sync(0xffffffffu, p, o); if (lane >= o) p += t; }
            wsum[lane] = p - v;
        }
        __syncthreads();
        int excl = carry_sh + wsum[wid] + (ws - s);
        int run = excl;
        #pragma unroll
        for (int j = 0; j < 8; j++) { int i = i0 + j; if (i < n) out[i] = run; run += vals[j]; }
        __syncthreads();
        if (tid == 1023) carry_sh = carry_sh + wsum[31] + ws;
        __syncthreads();
    }
    if (tid == 0) out[n] = carry_sh;
}

// ---------------- host ----------------
extern "C" void kernel_launch(void* const* d_in, const int* in_sizes, int n_in,
                              void* d_out, int out_size)
{
    (void)in_sizes; (void)n_in; (void)out_size;
    const float* x_post = (const float*)d_in[0];
    const float* x_user = (const float*)d_in[1];
    const float* x_ent  = (const float*)d_in[2];
    const float* post_w = (const float*)d_in[15];
    const float* post_b = (const float*)d_in[16];
    const float* user_w = (const float*)d_in[17];
    const float* user_b = (const float*)d_in[18];
    const float* ent_w  = (const float*)d_in[19];
    const float* ent_b  = (const float*)d_in[20];
    const float* W_src  = (const float*)d_in[21];
    const float* W_dst  = (const float*)d_in[22];
    const float* a_src  = (const float*)d_in[23];
    const float* a_dst  = (const float*)d_in[24];
    const float* gat_b  = (const float*)d_in[25];
    const float* cls_w1 = (const float*)d_in[26];
    const float* cls_b1 = (const float*)d_in[27];
    const float* cls_w2 = (const float*)d_in[28];
    const float* cls_b2 = (const float*)d_in[29];

    float *hA_post, *hB_post, *hA_user, *hB_user, *hA_ent, *hB_ent;
    float *hs, *als, *ald, *v, *h1;
    int *rowptr, *col, *deg, *cursor;
    cudaGetSymbolAddress((void**)&hA_post, g_hA_post);
    cudaGetSymbolAddress((void**)&hB_post, g_hB_post);
    cudaGetSymbolAddress((void**)&hA_user, g_hA_user);
    cudaGetSymbolAddress((void**)&hB_user, g_hB_user);
    cudaGetSymbolAddress((void**)&hA_ent,  g_hA_ent);
    cudaGetSymbolAddress((void**)&hB_ent,  g_hB_ent);
    cudaGetSymbolAddress((void**)&hs,  g_hs);
    cudaGetSymbolAddress((void**)&als, g_als);
    cudaGetSymbolAddress((void**)&ald, g_ald);
    cudaGetSymbolAddress((void**)&v,   g_v);
    cudaGetSymbolAddress((void**)&h1,  g_h1);
    cudaGetSymbolAddress((void**)&rowptr, g_rowptr);
    cudaGetSymbolAddress((void**)&col,    g_col);
    cudaGetSymbolAddress((void**)&deg,    g_deg);
    cudaGetSymbolAddress((void**)&cursor, g_cursor);

    // ---- build CSR (by dst) for each relation ----
    for (int r = 0; r < 6; r++) {
        const int* srcp = (const int*)d_in[REL_SRCIN[r]];
        const int* dstp = (const int*)d_in[REL_DSTIN[r]];
        int E = REL_E[r], Nd = REL_NDST[r];
        int* rp = rowptr + REL_RPOFF[r];
        int* cl = col + REL_COLOFF[r];
        cudaMemsetAsync(deg, 0, (size_t)Nd * sizeof(int));
        hist_k<<<(E + 255) / 256, 256>>>(dstp, deg, E);
        ex_scan<<<1, 1024>>>(deg, rp, Nd);
        cudaMemcpyAsync(cursor, rp, (size_t)Nd * sizeof(int), cudaMemcpyDeviceToDevice);
        scatter_k<<<(E + 255) / 256, 256>>>(srcp, dstp, cursor, cl, E);
    }

    // ---- input projections -> hA_* ----
    gemm_nt<<<dim3((NPOST + 63) / 64, 1), 256>>>(x_post, post_w, post_b, hA_post, NPOST, 64, 768, 0);
    gemm_nt<<<dim3((NUSER + 63) / 64, 1), 256>>>(x_user, user_w, user_b, hA_user, NUSER, 64, 32, 0);
    gemm_nt<<<dim3((NENT  + 63) / 64, 1), 256>>>(x_ent,  ent_w,  ent_b,  hA_ent,  NENT,  64, 64, 0);

    const int Nnode[3] = {NPOST, NUSER, NENT};
    float* cur[3] = {hA_post, hA_user, hA_ent};
    float* nxt[3] = {hB_post, hB_user, hB_ent};

    for (int l = 0; l < 2; l++) {
        for (int t = 0; t < 3; t++)
            cudaMemsetAsync(nxt[t], 0, (size_t)Nnode[t] * 64 * sizeof(float));
        for (int r = 0; r < 6; r++) {
            int lr = l * 6 + r;
            const float* Wsl = W_src + (size_t)lr * 128 * 64;
            const float* Wdl = W_dst + (size_t)lr * 128 * 64;
            const float* asl = a_src + (size_t)lr * 128;
            const float* adl = a_dst + (size_t)lr * 128;
            const float* bl  = gat_b + (size_t)lr * 64;
            float* hsrc = cur[REL_SRCT[r]];
            float* hdst = cur[REL_DSTT[r]];
            float* outp = nxt[REL_DSTT[r]];
            int Ns = Nnode[REL_SRCT[r]], Nd = Nnode[REL_DSTT[r]];

            compute_v<<<1, 256>>>(Wsl, Wdl, asl, adl, v);
            gemm_nt<<<dim3((Ns + 63) / 64, 2), 256>>>(hsrc, Wsl, nullptr, hs, Ns, 128, 64, 0);
            aldot<<<(Ns + 7) / 8, 256>>>(hsrc, v, als, Ns);
            aldot<<<(Nd + 7) / 8, 256>>>(hdst, v + 128, ald, Nd);
            gat_aggregate<<<(Nd + 7) / 8, 256>>>(rowptr + REL_RPOFF[r], col + REL_COLOFF[r],
                                                 hs, als, ald, bl, outp, Nd);
        }
        for (int t = 0; t < 3; t++)
            relu_k<<<(Nnode[t] * 64 + 255) / 256, 256>>>(nxt[t], Nnode[t] * 64);
        for (int t = 0; t < 3; t++) { float* tmp = cur[t]; cur[t] = nxt[t]; nxt[t] = tmp; }
    }

    // ---- classifier on posts ----
    gemm_nt<<<dim3((NPOST + 63) / 64, 1), 256>>>(cur[0], cls_w1, cls_b1, h1, NPOST, 32, 64, 1);
    cls2_k<<<(NPOST + 7) / 8, 256>>>(h1, cls_w2, cls_b2, (float*)d_out, NPOST);
}

// round 5
// speedup vs baseline: 1.3484x; 1.3484x over previous
#include <cuda_runtime.h>
#include <cuda_bf16.h>
#include <math.h>

// ---------------- problem constants ----------------
#define NPOST 100000
#define NUSER 50000
#define NENT  20000
#define NTOT  (NPOST + NUSER + NENT)

// relations: 0 publish(u->p), 1 repost(u->p), 2 contain(p->e),
//            3 interact(u->u), 4 follow(u->u), 5 similar(p->p)
static const int REL_E[6]    = {100000, 200000, 200000, 400000, 400000, 250000};
static const int REL_NDST[6] = {NPOST,  NPOST,  NENT,   NUSER,  NUSER,  NPOST};
static const int REL_SRCT[6] = {1,1,0,1,1,0};   // 0=post,1=user,2=ent
static const int REL_DSTT[6] = {0,0,2,1,1,0};
static const int REL_SRCIN[6] = {3,5,7,9,11,13};
static const int REL_DSTIN[6] = {4,6,8,10,12,14};
static const int REL_RPOFF[6] = {0, 100001, 200002, 220003, 270004, 320005};
static const int REL_COLOFF[6]= {0, 100000, 300000, 500000, 900000, 1300000};
#define RP_TOTAL  420006
#define DEG_TOTAL 420000
#define COL_TOTAL 1550000
#define EMAX      400000

__constant__ int c_E[6]      = {100000, 200000, 200000, 400000, 400000, 250000};
__constant__ int c_NDST[6]   = {NPOST, NPOST, NENT, NUSER, NUSER, NPOST};
__constant__ int c_DEGOFF[6] = {0, 100000, 200000, 220000, 270000, 320000};
__constant__ int c_RPOFF[6]  = {0, 100001, 200002, 220003, 270004, 320005};
__constant__ int c_COLOFF[6] = {0, 100000, 300000, 500000, 900000, 1300000};

// ---------------- device scratch (static, no allocation) ----------------
// node features, two ping-pong sets; layout: [post | user | ent], 64 ch each
__device__ __align__(16) float g_h0[NTOT * 64];
__device__ __align__(16) float g_h1b[NTOT * 64];
__device__ __align__(16) float g_hs[NPOST * 128];
__device__ __align__(16) float2 g_als[NPOST];
__device__ __align__(16) float2 g_ec[EMAX];
__device__ __align__(16) float g_vd[12 * 128];
__device__ __align__(16) float g_cls[NPOST * 32];
__device__ int g_rowptr[RP_TOTAL];
__device__ int g_col[COL_TOTAL];
__device__ int g_deg[DEG_TOTAL];
__device__ int g_cursor[RP_TOTAL];

struct EP { const int* src[6]; const int* dst[6]; };

// ---------------- f32x2 helpers ----------------
__device__ __forceinline__ void ffma2(unsigned long long& d, unsigned long long a, unsigned long long b) {
    asm("fma.rn.f32x2 %0, %1, %2, %0;" : "+l"(d) : "l"(a), "l"(b));
}
__device__ __forceinline__ unsigned long long pack2(float x, float y) {
    unsigned long long r; asm("mov.b64 %0, {%1, %2};" : "=l"(r) : "f"(x), "f"(y)); return r;
}
__device__ __forceinline__ float2 unpack2(unsigned long long v) {
    float2 r; asm("mov.b64 {%0, %1}, %2;" : "=f"(r.x), "=f"(r.y) : "l"(v)); return r;
}

// ---------------- GEMM: C[M,N] = A[M,K] @ W[N,K]^T (+bias, relu opt) ----------------
// 128x64 tile, 256 threads, 8 rows (4 packed pairs) x 4 cols per thread, f32x2 FMA.
// If als != null: also writes als[row*2 + blockIdx.y] = sum_c C_noBias[row][c]*aatt[n0+c].
// Requires K % 32 == 0.
__global__ void gemm2(const float* __restrict__ A, const float* __restrict__ W,
                      const float* __restrict__ bias, float* __restrict__ C,
                      int M, int N, int K, int ldc, int do_relu,
                      const float* __restrict__ aatt, float* __restrict__ als)
{
    __shared__ __align__(16) float As[32][130];   // [k][m], transposed
    __shared__ __align__(16) float Wk[32][65];    // [k][n]
    int tid = threadIdx.x;
    int tx = tid & 15, ty = tid >> 4;
    int m0 = blockIdx.x * 128, n0 = blockIdx.y * 64;

    unsigned long long acc[4][4];
    #pragma unroll
    for (int p = 0; p < 4; p++)
        #pragma unroll
        for (int j = 0; j < 4; j++) acc[p][j] = 0ull;  // (0.f,0.f)

    for (int k0 = 0; k0 < K; k0 += 32) {
        #pragma unroll
        for (int q = 0; q < 4; q++) {
            int idx = tid + q * 256;
            int m = idx >> 3, c4 = (idx & 7) * 4;
            float4 v = make_float4(0.f, 0.f, 0.f, 0.f);
            if (m0 + m < M) v = *(const float4*)(A + (size_t)(m0 + m) * K + k0 + c4);
            As[c4 + 0][m] = v.x; As[c4 + 1][m] = v.y; As[c4 + 2][m] = v.z; As[c4 + 3][m] = v.w;
        }
        #pragma unroll
        for (int q = 0; q < 2; q++) {
            int idx = tid + q * 256;
            int r = idx >> 3, c4 = (idx & 7) * 4;
            float4 v = make_float4(0.f, 0.f, 0.f, 0.f);
            if (n0 + r < N) v = *(const float4*)(W + (size_t)(n0 + r) * K + k0 + c4);
            Wk[c4 + 0][r] = v.x; Wk[c4 + 1][r] = v.y; Wk[c4 + 2][r] = v.z; Wk[c4 + 3][r] = v.w;
        }
        __syncthreads();
        #pragma unroll
        for (int k = 0; k < 32; k++) {
            unsigned long long a0 = *(const unsigned long long*)&As[k][ty * 8 + 0];
            unsigned long long a1 = *(const unsigned long long*)&As[k][ty * 8 + 2];
            unsigned long long a2 = *(const unsigned long long*)&As[k][ty * 8 + 4];
            unsigned long long a3 = *(const unsigned long long*)&As[k][ty * 8 + 6];
            float b0 = Wk[k][tx * 4 + 0], b1 = Wk[k][tx * 4 + 1];
            float b2 = Wk[k][tx * 4 + 2], b3 = Wk[k][tx * 4 + 3];
            unsigned long long d0 = pack2(b0, b0), d1 = pack2(b1, b1);
            unsigned long long d2 = pack2(b2, b2), d3 = pack2(b3, b3);
            ffma2(acc[0][0], a0, d0); ffma2(acc[0][1], a0, d1); ffma2(acc[0][2], a0, d2); ffma2(acc[0][3], a0, d3);
            ffma2(acc[1][0], a1, d0); ffma2(acc[1][1], a1, d1); ffma2(acc[1][2], a1, d2); ffma2(acc[1][3], a1, d3);
            ffma2(acc[2][0], a2, d0); ffma2(acc[2][1], a2, d1); ffma2(acc[2][2], a2, d2); ffma2(acc[2][3], a2, d3);
            ffma2(acc[3][0], a3, d0); ffma2(acc[3][1], a3, d1); ffma2(acc[3][2], a3, d2); ffma2(acc[3][3], a3, d3);
        }
        __syncthreads();
    }

    // attention logit epilogue (als = hs . a), computed pre-bias
    if (als) {
        float4 av = *(const float4*)(aatt + n0 + tx * 4);
        float rsum[8];
        #pragma unroll
        for (int p = 0; p < 4; p++) {
            unsigned long long s2 = 0ull;
            ffma2(s2, acc[p][0], pack2(av.x, av.x));
            ffma2(s2, acc[p][1], pack2(av.y, av.y));
            ffma2(s2, acc[p][2], pack2(av.z, av.z));
            ffma2(s2, acc[p][3], pack2(av.w, av.w));
            float2 u = unpack2(s2);
            rsum[2 * p] = u.x; rsum[2 * p + 1] = u.y;
        }
        #pragma unroll
        for (int o = 8; o; o >>= 1)
            #pragma unroll
            for (int i = 0; i < 8; i++)
                rsum[i] += __shfl_xor_sync(0xffffffffu, rsum[i], o);
        if (tx == 0) {
            #pragma unroll
            for (int i = 0; i < 8; i++) {
                int r = m0 + ty * 8 + i;
                if (r < M) als[r * 2 + blockIdx.y] = rsum[i];
            }
        }
    }

    bool cok = (n0 + tx * 4 + 3) < N;
    float4 bv = make_float4(0.f, 0.f, 0.f, 0.f);
    if (bias && cok) bv = *(const float4*)(bias + n0 + tx * 4);
    #pragma unroll
    for (int p = 0; p < 4; p++) {
        float2 u0 = unpack2(acc[p][0]), u1 = unpack2(acc[p][1]);
        float2 u2 = unpack2(acc[p][2]), u3 = unpack2(acc[p][3]);
        #pragma unroll
        for (int h = 0; h < 2; h++) {
            int r = m0 + ty * 8 + 2 * p + h;
            if (r >= M) continue;
            float v0 = h ? u0.y : u0.x, v1 = h ? u1.y : u1.x;
            float v2 = h ? u2.y : u2.x, v3 = h ? u3.y : u3.x;
            if (cok) {
                float4 o;
                o.x = v0 + bv.x; o.y = v1 + bv.y; o.z = v2 + bv.z; o.w = v3 + bv.w;
                if (do_relu) { o.x = fmaxf(o.x, 0.f); o.y = fmaxf(o.y, 0.f); o.z = fmaxf(o.z, 0.f); o.w = fmaxf(o.w, 0.f); }
                *(float4*)(C + (size_t)r * ldc + n0 + tx * 4) = o;
            } else {
                float vv[4] = {v0, v1, v2, v3};
                #pragma unroll
                for (int j = 0; j < 4; j++) {
                    int cn = n0 + tx * 4 + j;
                    if (cn < N) {
                        float val = vv[j] + (bias ? bias[cn] : 0.f);
                        if (do_relu) val = fmaxf(val, 0.f);
                        C[(size_t)r * ldc + cn] = val;
                    }
                }
            }
        }
    }
}

// vd[lr][h*64+k] = sum_c a_dst[lr][h][c] * W_dst[lr][(h*64+c)][k] — all 12 (l,r) at once
__global__ void compute_vd(const float* __restrict__ W_dst, const float* __restrict__ a_dst,
                           float* __restrict__ vd)
{
    int lr = blockIdx.x, t = threadIdx.x;
    int h = t >> 6, k = t & 63;
    const float* W = W_dst + (size_t)lr * 8192;
    const float* a = a_dst + (size_t)lr * 128 + h * 64;
    float s = 0.f;
    #pragma unroll 8
    for (int c = 0; c < 64; c++)
        s = fmaf(a[c], W[(h * 64 + c) * 64 + k], s);
    vd[lr * 128 + t] = s;
}

__device__ __forceinline__ float lrelu(float x) { return x > 0.f ? x : 0.2f * x; }

// warp per dst node: fused ald dot + online softmax (1 gathered pass, logits cached)
// + weighted aggregation. out[dst] += mean_heads(sum alpha*hs[src]) + bias
__global__ void gat_agg(const int* __restrict__ rowptr, const int* __restrict__ col,
                        const float* __restrict__ hs, const float2* __restrict__ als,
                        const float* __restrict__ hdst, const float* __restrict__ vd,
                        const float* __restrict__ bias, float* __restrict__ out,
                        float2* __restrict__ ec, int n_dst)
{
    int w = (blockIdx.x * blockDim.x + threadIdx.x) >> 5;
    int lane = threadIdx.x & 31;
    if (w >= n_dst) return;

    int beg = rowptr[w], end = rowptr[w + 1];
    if (beg == end) {
        if (lane < 16) {
            float4 bb = ((const float4*)bias)[lane];
            float* op = out + (size_t)w * 64 + lane * 4;
            op[0] += bb.x; op[1] += bb.y; op[2] += bb.z; op[3] += bb.w;
        }
        return;
    }

    // ald = hdst[w] . vd  (both heads), warp dot
    float2 x = *(const float2*)(hdst + (size_t)w * 64 + lane * 2);
    float ad0 = x.x * vd[lane * 2] + x.y * vd[lane * 2 + 1];
    float ad1 = x.x * vd[64 + lane * 2] + x.y * vd[64 + lane * 2 + 1];
    #pragma unroll
    for (int o = 16; o; o >>= 1) {
        ad0 += __shfl_xor_sync(0xffffffffu, ad0, o);
        ad1 += __shfl_xor_sync(0xffffffffu, ad1, o);
    }

    // pass A: gather als, compute logits -> cache; online (max,sum)
    float m0 = -1e30f, m1 = -1e30f, s0 = 0.f, s1 = 0.f;
    for (int e = beg + lane; e < end; e += 32) {
        float2 a2 = als[col[e]];
        float e0 = lrelu(a2.x + ad0);
        float e1 = lrelu(a2.y + ad1);
        ec[e] = make_float2(e0, e1);
        if (e0 > m0) { s0 = s0 * __expf(m0 - e0) + 1.f; m0 = e0; } else s0 += __expf(e0 - m0);
        if (e1 > m1) { s1 = s1 * __expf(m1 - e1) + 1.f; m1 = e1; } else s1 += __expf(e1 - m1);
    }
    #pragma unroll
    for (int o = 16; o; o >>= 1) {
        float om = __shfl_xor_sync(0xffffffffu, m0, o);
        float os = __shfl_xor_sync(0xffffffffu, s0, o);
        float nm = fmaxf(m0, om);
        s0 = s0 * __expf(m0 - nm) + os * __expf(om - nm); m0 = nm;
        om = __shfl_xor_sync(0xffffffffu, m1, o);
        os = __shfl_xor_sync(0xffffffffu, s1, o);
        nm = fmaxf(m1, om);
        s1 = s1 * __expf(m1 - nm) + os * __expf(om - nm); m1 = nm;
    }
    __syncwarp();

    int head = lane >> 4;
    float mh = head ? m1 : m0;
    float invh = 1.f / ((head ? s1 : s0) + 1e-16f);
    float a0 = 0.f, a1 = 0.f, a2 = 0.f, a3 = 0.f;
    for (int e = beg; e < end; e++) {
        int s = col[e];
        float2 ee = ec[e];
        float alpha = __expf((head ? ee.y : ee.x) - mh) * invh;
        float4 v = *(const float4*)(hs + (size_t)s * 128 + lane * 4);
        a0 = fmaf(alpha, v.x, a0);
        a1 = fmaf(alpha, v.y, a1);
        a2 = fmaf(alpha, v.z, a2);
        a3 = fmaf(alpha, v.w, a3);
    }
    a0 += __shfl_xor_sync(0xffffffffu, a0, 16);
    a1 += __shfl_xor_sync(0xffffffffu, a1, 16);
    a2 += __shfl_xor_sync(0xffffffffu, a2, 16);
    a3 += __shfl_xor_sync(0xffffffffu, a3, 16);
    if (lane < 16) {
        float4 bb = ((const float4*)bias)[lane];
        float* op = out + (size_t)w * 64 + lane * 4;
        op[0] += 0.5f * a0 + bb.x;
        op[1] += 0.5f * a1 + bb.y;
        op[2] += 0.5f * a2 + bb.z;
        op[3] += 0.5f * a3 + bb.w;
    }
}

__global__ void relu4(float4* __restrict__ x, int n4)
{
    int i = blockIdx.x * blockDim.x + threadIdx.x;
    if (i < n4) {
        float4 v = x[i];
        v.x = fmaxf(v.x, 0.f); v.y = fmaxf(v.y, 0.f);
        v.z = fmaxf(v.z, 0.f); v.w = fmaxf(v.w, 0.f);
        x[i] = v;
    }
}

// out[n] = b2 + dot(h1[n][0:32], w2); warp per row
__global__ void cls2_k(const float* __restrict__ h1, const float* __restrict__ w2,
                       const float* __restrict__ b2, float* __restrict__ out, int n)
{
    int w = (blockIdx.x * blockDim.x + threadIdx.x) >> 5;
    int lane = threadIdx.x & 31;
    if (w >= n) return;
    float p = h1[(size_t)w * 32 + lane] * w2[lane];
    #pragma unroll
    for (int o = 16; o; o >>= 1) p += __shfl_xor_sync(0xffffffffu, p, o);
    if (lane == 0) out[w] = p + b2[0];
}

// ---- batched CSR build ----
__global__ void hist_k(EP ep, int* __restrict__ deg)
{
    int r = blockIdx.y;
    int i = blockIdx.x * blockDim.x + threadIdx.x;
    if (i < c_E[r]) atomicAdd(&deg[c_DEGOFF[r] + ep.dst[r][i]], 1);
}

__global__ void scatter_k(EP ep, int* __restrict__ cursor, int* __restrict__ col)
{
    int r = blockIdx.y;
    int i = blockIdx.x * blockDim.x + threadIdx.x;
    if (i < c_E[r]) {
        int p = atomicAdd(&cursor[c_RPOFF[r] + ep.dst[r][i]], 1);
        col[c_COLOFF[r] + p] = ep.src[r][i];
    }
}

// block per relation: exclusive scan of its deg segment -> rowptr segment
__global__ void scan6(const int* __restrict__ degall, int* __restrict__ rpall)
{
    int rel = blockIdx.x;
    const int* in = degall + c_DEGOFF[rel];
    int* out = rpall + c_RPOFF[rel];
    int n = c_NDST[rel];

    __shared__ int wsum[32];
    __shared__ int carry_sh;
    int tid = threadIdx.x, lane = tid & 31, wid = tid >> 5;
    if (tid == 0) carry_sh = 0;
    __syncthreads();
    const int CH = 1024 * 8;
    for (int base = 0; base < n; base += CH) {
        int vals[8]; int s = 0;
        int i0 = base + tid * 8;
        #pragma unroll
        for (int j = 0; j < 8; j++) { int i = i0 + j; int v = (i < n) ? in[i] : 0; vals[j] = v; s += v; }
        int ws = s;
        #pragma unroll
        for (int o = 1; o < 32; o <<= 1) { int t = __shfl_up_sync(0xffffffffu, ws, o); if (lane >= o) ws += t; }
        if (lane == 31) wsum[wid] = ws;
        __syncthreads();
        if (wid == 0) {
            int v = wsum[lane], p = v;
            #pragma unroll
            for (int o = 1; o < 32; o <<= 1) { int t = __shfl_up_sync(0xffffffffu, p, o); if (lane >= o) p += t; }
            wsum[lane] = p - v;
        }
        __syncthreads();
        int excl = carry_sh + wsum[wid] + (ws - s);
        int run = excl;
        #pragma unroll
        for (int j = 0; j < 8; j++) { int i = i0 + j; if (i < n) out[i] = run; run += vals[j]; }
        __syncthreads();
        if (tid == 1023) carry_sh = carry_sh + wsum[31] + ws;
        __syncthreads();
    }
    if (tid == 0) out[n] = carry_sh;
}

// ---------------- host ----------------
extern "C" void kernel_launch(void* const* d_in, const int* in_sizes, int n_in,
                              void* d_out, int out_size)
{
    (void)in_sizes; (void)n_in; (void)out_size;
    const float* x_post = (const float*)d_in[0];
    const float* x_user = (const float*)d_in[1];
    const float* x_ent  = (const float*)d_in[2];
    const float* post_w = (const float*)d_in[15];
    const float* post_b = (const float*)d_in[16];
    const float* user_w = (const float*)d_in[17];
    const float* user_b = (const float*)d_in[18];
    const float* ent_w  = (const float*)d_in[19];
    const float* ent_b  = (const float*)d_in[20];
    const float* W_src  = (const float*)d_in[21];
    const float* W_dst  = (const float*)d_in[22];
    const float* a_src  = (const float*)d_in[23];
    const float* a_dst  = (const float*)d_in[25 - 1]; // d_in[24]
    const float* gat_b  = (const float*)d_in[25];
    const float* cls_w1 = (const float*)d_in[26];
    const float* cls_b1 = (const float*)d_in[27];
    const float* cls_w2 = (const float*)d_in[28];
    const float* cls_b2 = (const float*)d_in[29];

    float *h0, *h1b, *hs, *vd, *clsbuf;
    float2 *als, *ec;
    int *rowptr, *col, *deg, *cursor;
    cudaGetSymbolAddress((void**)&h0, g_h0);
    cudaGetSymbolAddress((void**)&h1b, g_h1b);
    cudaGetSymbolAddress((void**)&hs, g_hs);
    cudaGetSymbolAddress((void**)&als, g_als);
    cudaGetSymbolAddress((void**)&ec, g_ec);
    cudaGetSymbolAddress((void**)&vd, g_vd);
    cudaGetSymbolAddress((void**)&clsbuf, g_cls);
    cudaGetSymbolAddress((void**)&rowptr, g_rowptr);
    cudaGetSymbolAddress((void**)&col, g_col);
    cudaGetSymbolAddress((void**)&deg, g_deg);
    cudaGetSymbolAddress((void**)&cursor, g_cursor);

    // ---- CSR build (all relations batched) ----
    EP ep;
    for (int r = 0; r < 6; r++) {
        ep.src[r] = (const int*)d_in[REL_SRCIN[r]];
        ep.dst[r] = (const int*)d_in[REL_DSTIN[r]];
    }
    cudaMemsetAsync(deg, 0, DEG_TOTAL * sizeof(int));
    hist_k<<<dim3((EMAX + 255) / 256, 6), 256>>>(ep, deg);
    scan6<<<6, 1024>>>(deg, rowptr);
    cudaMemcpyAsync(cursor, rowptr, RP_TOTAL * sizeof(int), cudaMemcpyDeviceToDevice);
    scatter_k<<<dim3((EMAX + 255) / 256, 6), 256>>>(ep, cursor, col);

    // ---- vd for all 12 (layer, relation) ----
    compute_vd<<<12, 128>>>(W_dst, a_dst, vd);

    // ---- input projections ----
    float* hp = h0;                       // posts at offset 0
    float* hu = h0 + (size_t)NPOST * 64;  // users
    float* he = h0 + (size_t)(NPOST + NUSER) * 64;
    gemm2<<<dim3((NPOST + 127) / 128, 1), 256>>>(x_post, post_w, post_b, hp, NPOST, 64, 768, 64, 0, nullptr, nullptr);
    gemm2<<<dim3((NUSER + 127) / 128, 1), 256>>>(x_user, user_w, user_b, hu, NUSER, 64, 32, 64, 0, nullptr, nullptr);
    gemm2<<<dim3((NENT  + 127) / 128, 1), 256>>>(x_ent,  ent_w,  ent_b,  he, NENT, 64, 64, 64, 0, nullptr, nullptr);

    const int Nnode[3] = {NPOST, NUSER, NENT};
    const size_t toff[3] = {0, (size_t)NPOST * 64, (size_t)(NPOST + NUSER) * 64};
    float* cur = h0;
    float* nxt = h1b;

    for (int l = 0; l < 2; l++) {
        cudaMemsetAsync(nxt, 0, (size_t)NTOT * 64 * sizeof(float));
        for (int r = 0; r < 6; r++) {
            int lr = l * 6 + r;
            const float* Wsl = W_src + (size_t)lr * 128 * 64;
            const float* asl = a_src + (size_t)lr * 128;
            const float* bl  = gat_b + (size_t)lr * 64;
            const float* hsrc = cur + toff[REL_SRCT[r]];
            const float* hdst = cur + toff[REL_DSTT[r]];
            float* outp = nxt + toff[REL_DSTT[r]];
            int Ns = Nnode[REL_SRCT[r]], Nd = Nnode[REL_DSTT[r]];

            // hs = hsrc @ Wsl^T, fused als epilogue
            gemm2<<<dim3((Ns + 127) / 128, 2), 256>>>(hsrc, Wsl, nullptr, hs, Ns, 128, 64, 128, 0,
                                                      asl, (float*)als);
            gat_agg<<<(Nd + 7) / 8, 256>>>(rowptr + REL_RPOFF[r], col + REL_COLOFF[r],
                                           hs, als, hdst, vd + lr * 128, bl, outp, ec, Nd);
        }
        relu4<<<((NTOT * 64 / 4) + 255) / 256, 256>>>((float4*)nxt, NTOT * 64 / 4);
        float* tmp = cur; cur = nxt; nxt = tmp;
    }

    // ---- classifier on posts ----
    gemm2<<<dim3((NPOST + 127) / 128, 1), 256>>>(cur, cls_w1, cls_b1, clsbuf, NPOST, 32, 64, 32, 1, nullptr, nullptr);
    cls2_k<<<(NPOST + 7) / 8, 256>>>(clsbuf, cls_w2, cls_b2, (float*)d_out, NPOST);
}